// round 7
// baseline (speedup 1.0000x reference)
#include <cuda_runtime.h>
#include <cuda_fp16.h>
#include <math.h>

#define NODES 100000
#define EDGES_MAX 1600000
#define FEAT  128
#define SCAN_B 256
#define NBLK_SCAN ((NODES + SCAN_B - 1) / SCAN_B)   // 391

// Scratch: __device__ globals (allocation-free rule). Device-side use only.
__device__ __half g_half[NODES * FEAT];  // g = (in @ W) * dinv, fp16 for gather
__device__ float  g_h[NODES * FEAT];     // layer output (fp32, GEMM input)
__device__ float  g_dinv[NODES];
__device__ int    g_cnt[NODES];          // in-degree histogram (no self loop)
__device__ int    g_incl[NODES];
__device__ int    g_rowstart[NODES];
__device__ int    g_cur[NODES];
__device__ int    g_poff[NBLK_SCAN + 1];
__device__ int    g_csr[EDGES_MAX];      // src indices grouped by dst
__device__ int    g_idx64;

// ---------------------------------------------------------------------------
// init: zero histogram; block 0 detects edge-index dtype.
// ---------------------------------------------------------------------------
__global__ void k_init(const void* __restrict__ ei, int n) {
    int i = blockIdx.x * blockDim.x + threadIdx.x;
    if (i < n) g_cnt[i] = 0;
    if (blockIdx.x == 0) {
        __shared__ int ok;
        if (threadIdx.x == 0) ok = 1;
        __syncthreads();
        long long v = ((const long long*)ei)[threadIdx.x];
        if (v < 0 || v >= NODES) ok = 0;
        __syncthreads();
        if (threadIdx.x == 0) g_idx64 = ok;
    }
}

__device__ __forceinline__ int load_idx(const void* ei, long long elem) {
    if (g_idx64) return (int)((const long long*)ei)[elem];
    return ((const int*)ei)[elem];
}

// ---------------------------------------------------------------------------
// CSR build
// ---------------------------------------------------------------------------
__global__ void k_hist(const void* __restrict__ ei, int E) {
    int e = blockIdx.x * blockDim.x + threadIdx.x;
    if (e >= E) return;
    int d = load_idx(ei, (long long)E + e);
    if ((unsigned)d < NODES) atomicAdd(&g_cnt[d], 1);
}

__global__ void k_dinv(int n) {
    int i = blockIdx.x * blockDim.x + threadIdx.x;
    if (i < n) g_dinv[i] = rsqrtf((float)g_cnt[i] + 1.0f);
}

__global__ void k_scan1(int n) {
    __shared__ int sm[SCAN_B];
    int i = blockIdx.x * SCAN_B + threadIdx.x;
    int v = (i < n) ? g_cnt[i] : 0;
    sm[threadIdx.x] = v;
    __syncthreads();
#pragma unroll
    for (int o = 1; o < SCAN_B; o <<= 1) {
        int t = (threadIdx.x >= o) ? sm[threadIdx.x - o] : 0;
        __syncthreads();
        sm[threadIdx.x] += t;
        __syncthreads();
    }
    if (i < n) g_incl[i] = sm[threadIdx.x];
    if (threadIdx.x == SCAN_B - 1) g_poff[blockIdx.x] = sm[SCAN_B - 1];
}

__global__ void k_scan2() {
    __shared__ int sm[512];
    int i = threadIdx.x;
    int v = (i < NBLK_SCAN) ? g_poff[i] : 0;
    sm[i] = v;
    __syncthreads();
#pragma unroll
    for (int o = 1; o < 512; o <<= 1) {
        int t = (i >= o) ? sm[i - o] : 0;
        __syncthreads();
        sm[i] += t;
        __syncthreads();
    }
    if (i < NBLK_SCAN) g_poff[i] = sm[i] - v;   // exclusive
}

__global__ void k_scan3(int n) {
    int i = blockIdx.x * blockDim.x + threadIdx.x;
    if (i >= n) return;
    int c = g_cnt[i];
    int rs = g_incl[i] - c + g_poff[i >> 8];
    g_rowstart[i] = rs;
    g_cur[i] = rs;
}

__global__ void k_place(const void* __restrict__ ei, int E) {
    int e = blockIdx.x * blockDim.x + threadIdx.x;
    if (e >= E) return;
    int s = load_idx(ei, e);
    int d = load_idx(ei, (long long)E + e);
    if ((unsigned)s >= NODES || (unsigned)d >= NODES) return;
    int pos = atomicAdd(&g_cur[d], 1);
    g_csr[pos] = s;
}

// ---------------------------------------------------------------------------
// tf32 tensor-core GEMM, fragment-major smem staging:
//   g_half[row][c] = fp16( (sum_k A[row][k] * W[k][c]) * dinv[row] )
// BM=128, BN=128, BK=32 (4 chunks). 8 warps, warp tile 64x32 (mt=4, nt=4).
// A frag = LDS.128, B frag = LDS.64, both conflict-free.
// ---------------------------------------------------------------------------
__device__ __forceinline__ float to_tf32(float x) {
    unsigned u;
    asm("cvt.rna.tf32.f32 %0, %1;" : "=r"(u) : "f"(x));
    return __uint_as_float(u);
}

__global__ void __launch_bounds__(256)
k_gemm_tf32(const float* __restrict__ Aext, const float* __restrict__ W,
            int n, int use_h) {
    // A frag-major: [ks(4)][r16(8)][gq(8)][tq(4)][4 floats]  = 4096 floats
    // B frag-major: [ks(4)][col(128)][tq(4)][2 floats]        = 4096 floats
    __shared__ float As[4096];
    __shared__ float Bs[4096];

    const float* A = use_h ? (const float*)g_h : Aext;

    int tid  = threadIdx.x;
    int wid  = tid >> 5;
    int lane = tid & 31;
    int gq   = lane >> 2;
    int tq   = lane & 3;
    int warp_m = wid & 1;    // 2 warps along M: rows 64*warp_m..+63
    int warp_n = wid >> 1;   // 4 warps along N: cols 32*warp_n..+31
    int row0 = blockIdx.x * 128;

    const float4* A4 = (const float4*)A;
    const float4* W4 = (const float4*)W;

    float acc[4][4][4];
#pragma unroll
    for (int mt = 0; mt < 4; mt++)
#pragma unroll
        for (int nt = 0; nt < 4; nt++)
#pragma unroll
            for (int r = 0; r < 4; r++) acc[mt][nt][r] = 0.f;

    for (int kc = 0; kc < 4; kc++) {
        // ---- stage A chunk [128 rows][32 k] into frag-major layout ----
#pragma unroll
        for (int i = 0; i < 4; i++) {
            int slot = tid + i * 256;            // 0..1023
            int r  = slot >> 3;                  // row 0..127
            int c4 = slot & 7;                   // float4 in k-chunk
            int gr = row0 + r;
            float4 v = (gr < n) ? A4[gr * 32 + kc * 8 + c4]
                                : make_float4(0.f, 0.f, 0.f, 0.f);
            int ks   = c4 >> 1;
            int half = c4 & 1;                   // k in [0,4) or [4,8) of group
            int r16  = r >> 4;
            int gqw  = r & 7;
            int a01  = (r >> 3) & 1;
            int elem = half * 2 + a01;           // a0/a1/a2/a3 slot
            int base = ((ks * 8 + r16) * 8 + gqw) * 16 + elem;
            As[base + 0]  = to_tf32(v.x);        // tq = 0..3 -> +4 each
            As[base + 4]  = to_tf32(v.y);
            As[base + 8]  = to_tf32(v.z);
            As[base + 12] = to_tf32(v.w);
        }
        // ---- stage W chunk [32 k][128 cols] into frag-major layout ----
#pragma unroll
        for (int i = 0; i < 4; i++) {
            int slot = tid + i * 256;
            int kr = slot >> 5;                  // k-row 0..31
            int c4 = slot & 31;                  // float4 col group
            float4 v = W4[(kc * 32 + kr) * 32 + c4];
            int ks   = kr >> 3;
            int tqs  = kr & 3;
            int elem = (kr >> 2) & 1;            // b0 / b1
            int col0 = c4 * 4;
            Bs[((ks * 128 + col0 + 0) * 4 + tqs) * 2 + elem] = to_tf32(v.x);
            Bs[((ks * 128 + col0 + 1) * 4 + tqs) * 2 + elem] = to_tf32(v.y);
            Bs[((ks * 128 + col0 + 2) * 4 + tqs) * 2 + elem] = to_tf32(v.z);
            Bs[((ks * 128 + col0 + 3) * 4 + tqs) * 2 + elem] = to_tf32(v.w);
        }
        __syncthreads();

#pragma unroll
        for (int ks = 0; ks < 4; ks++) {
            float4 a[4];
#pragma unroll
            for (int mt = 0; mt < 4; mt++) {
                int r16 = warp_m * 4 + mt;
                a[mt] = *(const float4*)&As[((ks * 8 + r16) * 8 + gq) * 16 + tq * 4];
            }
            float2 bfr[4];
#pragma unroll
            for (int nt = 0; nt < 4; nt++) {
                int col = warp_n * 32 + nt * 8 + gq;
                bfr[nt] = *(const float2*)&Bs[((ks * 128 + col) * 4 + tq) * 2];
            }
#pragma unroll
            for (int nt = 0; nt < 4; nt++) {
#pragma unroll
                for (int mt = 0; mt < 4; mt++) {
                    asm volatile(
                        "mma.sync.aligned.m16n8k8.row.col.f32.tf32.tf32.f32 "
                        "{%0,%1,%2,%3}, {%4,%5,%6,%7}, {%8,%9}, {%0,%1,%2,%3};"
                        : "+f"(acc[mt][nt][0]), "+f"(acc[mt][nt][1]),
                          "+f"(acc[mt][nt][2]), "+f"(acc[mt][nt][3])
                        : "r"(__float_as_uint(a[mt].x)),
                          "r"(__float_as_uint(a[mt].y)),
                          "r"(__float_as_uint(a[mt].z)),
                          "r"(__float_as_uint(a[mt].w)),
                          "r"(__float_as_uint(bfr[nt].x)),
                          "r"(__float_as_uint(bfr[nt].y)));
                }
            }
        }
        __syncthreads();
    }

    // epilogue: scale by dinv, convert to fp16, write g_half
#pragma unroll
    for (int mt = 0; mt < 4; mt++) {
        int rlo = row0 + warp_m * 64 + mt * 16 + gq;
        int rhi = rlo + 8;
        float dlo = (rlo < n) ? g_dinv[rlo] : 0.f;
        float dhi = (rhi < n) ? g_dinv[rhi] : 0.f;
#pragma unroll
        for (int nt = 0; nt < 4; nt++) {
            int c = warp_n * 32 + nt * 8 + 2 * tq;
            if (rlo < n)
                *(__half2*)&g_half[rlo * 128 + c] =
                    __floats2half2_rn(acc[mt][nt][0] * dlo, acc[mt][nt][1] * dlo);
            if (rhi < n)
                *(__half2*)&g_half[rhi * 128 + c] =
                    __floats2half2_rn(acc[mt][nt][2] * dhi, acc[mt][nt][3] * dhi);
        }
    }
}

// ---------------------------------------------------------------------------
// Aggregate (warp per node, fp16 gather, fp32 accumulate):
//   acc = g[i] + sum_{e in CSR row i} g[src_e];  h = relu(dinv_i*acc + b)
// FINAL=1 fuses FC + log_softmax.
// ---------------------------------------------------------------------------
__device__ __forceinline__ void add_row(float4& acc, uint2 v) {
    float2 p0 = __half22float2(*(__half2*)&v.x);
    float2 p1 = __half22float2(*(__half2*)&v.y);
    acc.x += p0.x; acc.y += p0.y; acc.z += p1.x; acc.w += p1.y;
}

template <int FINAL>
__global__ void k_agg(const float* __restrict__ b,
                      const float* __restrict__ Wfc,
                      const float* __restrict__ bfc,
                      float* __restrict__ out,
                      int n) {
    int widx = (blockIdx.x * blockDim.x + threadIdx.x) >> 5;
    int q = threadIdx.x & 31;
    if (widx >= n) return;

    const uint2* gh = (const uint2*)g_half;   // 32 x 8B per row
    int base = g_rowstart[widx];
    int end  = base + g_cnt[widx];

    float4 acc = make_float4(0.f, 0.f, 0.f, 0.f);
    add_row(acc, gh[widx * 32 + q]);          // self-loop term

    int e = base;
    for (; e + 4 <= end; e += 4) {
        int s0 = g_csr[e];
        int s1 = g_csr[e + 1];
        int s2 = g_csr[e + 2];
        int s3 = g_csr[e + 3];
        uint2 v0 = gh[s0 * 32 + q];
        uint2 v1 = gh[s1 * 32 + q];
        uint2 v2 = gh[s2 * 32 + q];
        uint2 v3 = gh[s3 * 32 + q];
        add_row(acc, v0); add_row(acc, v1);
        add_row(acc, v2); add_row(acc, v3);
    }
    for (; e < end; e++) add_row(acc, gh[g_csr[e] * 32 + q]);

    float dv = g_dinv[widx];
    float4 bb = ((const float4*)b)[q];
    float4 h;
    h.x = fmaxf(dv * acc.x + bb.x, 0.f);
    h.y = fmaxf(dv * acc.y + bb.y, 0.f);
    h.z = fmaxf(dv * acc.z + bb.z, 0.f);
    h.w = fmaxf(dv * acc.w + bb.w, 0.f);

    if (!FINAL) {
        ((float4*)g_h)[widx * 32 + q] = h;
    } else {
        const float4* w4 = (const float4*)Wfc;   // [128][2]: 2 rows per float4
        float4 w0 = w4[q * 2];
        float4 w1 = w4[q * 2 + 1];
        float l0 = h.x * w0.x + h.y * w0.z + h.z * w1.x + h.w * w1.z;
        float l1 = h.x * w0.y + h.y * w0.w + h.z * w1.y + h.w * w1.w;
#pragma unroll
        for (int o = 16; o > 0; o >>= 1) {
            l0 += __shfl_xor_sync(0xffffffffu, l0, o);
            l1 += __shfl_xor_sync(0xffffffffu, l1, o);
        }
        if (q == 0) {
            l0 += bfc[0];
            l1 += bfc[1];
            float m = fmaxf(l0, l1);
            float z = m + logf(expf(l0 - m) + expf(l1 - m));
            out[widx * 2]     = l0 - z;
            out[widx * 2 + 1] = l1 - z;
        }
    }
}

// ---------------------------------------------------------------------------
extern "C" void kernel_launch(void* const* d_in, const int* in_sizes, int n_in,
                              void* d_out, int out_size) {
    const float* x   = (const float*)d_in[0];
    const void*  ei  = d_in[1];
    const float* W1  = (const float*)d_in[2];
    const float* b1  = (const float*)d_in[3];
    const float* W2  = (const float*)d_in[4];
    const float* b2  = (const float*)d_in[5];
    const float* Wfc = (const float*)d_in[6];
    const float* bfc = (const float*)d_in[7];
    float*       out = (float*)d_out;

    int n = in_sizes[0] / FEAT;
    int E = in_sizes[1] / 2;

    int tb = 256;
    int node_blocks = (n + tb - 1) / tb;
    int edge_blocks = (E + tb - 1) / tb;
    int gemm_blocks = (n + 127) / 128;
    int warp_blocks = (int)(((long long)n * 32 + tb - 1) / tb);

    // 1-3: histogram + dinv
    k_init<<<node_blocks, tb>>>(ei, n);
    k_hist<<<edge_blocks, tb>>>(ei, E);
    k_dinv<<<node_blocks, tb>>>(n);

    // 4: layer-1 GEMM (profiled launch)
    k_gemm_tf32<<<gemm_blocks, tb>>>(x, W1, n, 0);

    // 5-8: CSR finalize
    k_scan1<<<NBLK_SCAN, SCAN_B>>>(n);
    k_scan2<<<1, 512>>>();
    k_scan3<<<node_blocks, tb>>>(n);
    k_place<<<edge_blocks, tb>>>(ei, E);

    // 9: layer-1 aggregate
    k_agg<0><<<warp_blocks, tb>>>(b1, nullptr, nullptr, nullptr, n);

    // 10-11: layer 2 + fused FC/log_softmax
    k_gemm_tf32<<<gemm_blocks, tb>>>(x, W2, n, 1);
    k_agg<1><<<warp_blocks, tb>>>(b2, Wfc, bfc, out, n);
}

// round 8
// speedup vs baseline: 1.6397x; 1.6397x over previous
#include <cuda_runtime.h>
#include <cuda_fp16.h>
#include <math.h>

#define NODES 100000
#define EDGES_MAX 1600000
#define FEAT  128
#define SCAN_B 256
#define NBLK_SCAN ((NODES + SCAN_B - 1) / SCAN_B)   // 391

// Scratch: __device__ globals (allocation-free rule). Device-side use only.
__device__ __half g_half[NODES * FEAT];  // g = (in @ W) * dinv  (agg gather src)
__device__ __half g_h2[NODES * FEAT];    // layer-1 output h (GEMM-2 input)
__device__ float  g_dinv[NODES];
__device__ int    g_cnt[NODES];
__device__ int    g_incl[NODES];
__device__ int    g_rowstart[NODES];
__device__ int    g_cur[NODES];
__device__ int    g_poff[NBLK_SCAN + 1];
__device__ int    g_csr[EDGES_MAX];
__device__ int    g_idx64;

// ---------------------------------------------------------------------------
__global__ void k_init(const void* __restrict__ ei, int n) {
    int i = blockIdx.x * blockDim.x + threadIdx.x;
    if (i < n) g_cnt[i] = 0;
    if (blockIdx.x == 0) {
        __shared__ int ok;
        if (threadIdx.x == 0) ok = 1;
        __syncthreads();
        long long v = ((const long long*)ei)[threadIdx.x];
        if (v < 0 || v >= NODES) ok = 0;
        __syncthreads();
        if (threadIdx.x == 0) g_idx64 = ok;
    }
}

__device__ __forceinline__ int load_idx(const void* ei, long long elem) {
    if (g_idx64) return (int)((const long long*)ei)[elem];
    return ((const int*)ei)[elem];
}

// ---------------------------------------------------------------------------
// CSR build
// ---------------------------------------------------------------------------
__global__ void k_hist(const void* __restrict__ ei, int E) {
    int e = blockIdx.x * blockDim.x + threadIdx.x;
    if (e >= E) return;
    int d = load_idx(ei, (long long)E + e);
    if ((unsigned)d < NODES) atomicAdd(&g_cnt[d], 1);
}

__global__ void k_dinv(int n) {
    int i = blockIdx.x * blockDim.x + threadIdx.x;
    if (i < n) g_dinv[i] = rsqrtf((float)g_cnt[i] + 1.0f);
}

__global__ void k_scan1(int n) {
    __shared__ int sm[SCAN_B];
    int i = blockIdx.x * SCAN_B + threadIdx.x;
    int v = (i < n) ? g_cnt[i] : 0;
    sm[threadIdx.x] = v;
    __syncthreads();
#pragma unroll
    for (int o = 1; o < SCAN_B; o <<= 1) {
        int t = (threadIdx.x >= o) ? sm[threadIdx.x - o] : 0;
        __syncthreads();
        sm[threadIdx.x] += t;
        __syncthreads();
    }
    if (i < n) g_incl[i] = sm[threadIdx.x];
    if (threadIdx.x == SCAN_B - 1) g_poff[blockIdx.x] = sm[SCAN_B - 1];
}

__global__ void k_scan2() {
    __shared__ int sm[512];
    int i = threadIdx.x;
    int v = (i < NBLK_SCAN) ? g_poff[i] : 0;
    sm[i] = v;
    __syncthreads();
#pragma unroll
    for (int o = 1; o < 512; o <<= 1) {
        int t = (i >= o) ? sm[i - o] : 0;
        __syncthreads();
        sm[i] += t;
        __syncthreads();
    }
    if (i < NBLK_SCAN) g_poff[i] = sm[i] - v;   // exclusive
}

__global__ void k_scan3(int n) {
    int i = blockIdx.x * blockDim.x + threadIdx.x;
    if (i >= n) return;
    int c = g_cnt[i];
    int rs = g_incl[i] - c + g_poff[i >> 8];
    g_rowstart[i] = rs;
    g_cur[i] = rs;
}

__global__ void k_place(const void* __restrict__ ei, int E) {
    int e = blockIdx.x * blockDim.x + threadIdx.x;
    if (e >= E) return;
    int s = load_idx(ei, e);
    int d = load_idx(ei, (long long)E + e);
    if ((unsigned)s >= NODES || (unsigned)d >= NODES) return;
    int pos = atomicAdd(&g_cur[d], 1);
    g_csr[pos] = s;
}

// ---------------------------------------------------------------------------
// fp16 tensor-core GEMM via ldmatrix + mma.m16n8k16:
//   g_half[row][c] = fp16( (sum_k A[row][k] * W[k][c]) * dinv[row] )
// BM=128, BN=128, BK=32 (4 chunks). 8 warps (2x4), warp tile 64x32.
// A: [128][40] halfs (stride 80B, ldmatrix conflict-free).
// W: [32][136] halfs (stride 272B, ldmatrix.trans conflict-free).
// ---------------------------------------------------------------------------
#define SA 40
#define SB 136

__global__ void __launch_bounds__(256)
k_gemm_f16(const float* __restrict__ Aext, const float* __restrict__ W,
           int n, int use_h) {
    __shared__ __half As[128 * SA];   // 10240 B
    __shared__ __half Ws[32 * SB];    //  8704 B

    int tid  = threadIdx.x;
    int wid  = tid >> 5;
    int lane = tid & 31;
    int gq   = lane >> 2;
    int tq   = lane & 3;
    int warp_m = wid & 1;    // rows 64*warp_m .. +63
    int warp_n = wid >> 1;   // cols 32*warp_n .. +31
    int row0 = blockIdx.x * 128;

    const float4* A4  = (const float4*)Aext;
    const uint2*  H2  = (const uint2*)g_h2;
    const float4* W4  = (const float4*)W;

    float acc[4][4][4];
#pragma unroll
    for (int mt = 0; mt < 4; mt++)
#pragma unroll
        for (int j = 0; j < 4; j++)
#pragma unroll
            for (int r = 0; r < 4; r++) acc[mt][j][r] = 0.f;

    // ldmatrix source addresses (fixed per thread across chunks)
    unsigned a_addr[2];   // per ks2: row = warp_m*64 + (lane&15) [+mt*16], k = ks2*16 + ((lane>>4)&1)*8
    unsigned b_addr[2][2];
    {
        int arow = (lane & 15);
        int akof = ((lane >> 4) & 1) * 8;
#pragma unroll
        for (int ks2 = 0; ks2 < 2; ks2++)
            a_addr[ks2] = (unsigned)__cvta_generic_to_shared(
                &As[(warp_m * 64 + arow) * SA + ks2 * 16 + akof]);
        int krow = (lane & 15);
        int nof  = ((lane >> 4) & 1) * 8;
#pragma unroll
        for (int ks2 = 0; ks2 < 2; ks2++)
#pragma unroll
            for (int nt2 = 0; nt2 < 2; nt2++)
                b_addr[ks2][nt2] = (unsigned)__cvta_generic_to_shared(
                    &Ws[(ks2 * 16 + krow) * SB + warp_n * 32 + nt2 * 16 + nof]);
    }

    for (int kc = 0; kc < 4; kc++) {
        // ---- stage A chunk [128 rows][32 k] as fp16 ----
#pragma unroll
        for (int i = 0; i < 4; i++) {
            int slot = tid + i * 256;          // 0..1023
            int r  = slot >> 3;                // row
            int c4 = slot & 7;                 // 4-elem group in chunk
            int gr = row0 + r;
            uint2 d = make_uint2(0u, 0u);
            if (gr < n) {
                if (use_h) {
                    d = H2[gr * 32 + kc * 8 + c4];
                } else {
                    float4 v = A4[gr * 32 + kc * 8 + c4];
                    *(__half2*)&d.x = __floats2half2_rn(v.x, v.y);
                    *(__half2*)&d.y = __floats2half2_rn(v.z, v.w);
                }
            }
            *(uint2*)&As[r * SA + c4 * 4] = d;
        }
        // ---- stage W chunk [32 k][128 n] as fp16 ----
#pragma unroll
        for (int i = 0; i < 4; i++) {
            int slot = tid + i * 256;
            int kr = slot >> 5;
            int c4 = slot & 31;
            float4 v = W4[(kc * 32 + kr) * 32 + c4];
            uint2 d;
            *(__half2*)&d.x = __floats2half2_rn(v.x, v.y);
            *(__half2*)&d.y = __floats2half2_rn(v.z, v.w);
            *(uint2*)&Ws[kr * SB + c4 * 4] = d;
        }
        __syncthreads();

#pragma unroll
        for (int ks2 = 0; ks2 < 2; ks2++) {
            unsigned a[4][4];
#pragma unroll
            for (int mt = 0; mt < 4; mt++) {
                unsigned addr = a_addr[ks2] + mt * 16 * SA * 2;   // +16 rows
                asm volatile(
                    "ldmatrix.sync.aligned.m8n8.x4.shared.b16 {%0,%1,%2,%3}, [%4];"
                    : "=r"(a[mt][0]), "=r"(a[mt][1]), "=r"(a[mt][2]), "=r"(a[mt][3])
                    : "r"(addr));
            }
            unsigned b[2][4];
#pragma unroll
            for (int nt2 = 0; nt2 < 2; nt2++) {
                asm volatile(
                    "ldmatrix.sync.aligned.m8n8.x4.trans.shared.b16 {%0,%1,%2,%3}, [%4];"
                    : "=r"(b[nt2][0]), "=r"(b[nt2][1]), "=r"(b[nt2][2]), "=r"(b[nt2][3])
                    : "r"(b_addr[ks2][nt2]));
            }
#pragma unroll
            for (int nt2 = 0; nt2 < 2; nt2++) {
#pragma unroll
                for (int half8 = 0; half8 < 2; half8++) {
                    int j = nt2 * 2 + half8;
#pragma unroll
                    for (int mt = 0; mt < 4; mt++) {
                        asm volatile(
                            "mma.sync.aligned.m16n8k16.row.col.f32.f16.f16.f32 "
                            "{%0,%1,%2,%3}, {%4,%5,%6,%7}, {%8,%9}, {%0,%1,%2,%3};"
                            : "+f"(acc[mt][j][0]), "+f"(acc[mt][j][1]),
                              "+f"(acc[mt][j][2]), "+f"(acc[mt][j][3])
                            : "r"(a[mt][0]), "r"(a[mt][1]),
                              "r"(a[mt][2]), "r"(a[mt][3]),
                              "r"(b[nt2][half8 * 2]), "r"(b[nt2][half8 * 2 + 1]));
                    }
                }
            }
        }
        __syncthreads();
    }

    // epilogue: scale by dinv, convert to fp16, write g_half
#pragma unroll
    for (int mt = 0; mt < 4; mt++) {
        int rlo = row0 + warp_m * 64 + mt * 16 + gq;
        int rhi = rlo + 8;
        float dlo = (rlo < n) ? g_dinv[rlo] : 0.f;
        float dhi = (rhi < n) ? g_dinv[rhi] : 0.f;
#pragma unroll
        for (int j = 0; j < 4; j++) {
            int c = warp_n * 32 + j * 8 + 2 * tq;
            if (rlo < n)
                *(__half2*)&g_half[rlo * 128 + c] =
                    __floats2half2_rn(acc[mt][j][0] * dlo, acc[mt][j][1] * dlo);
            if (rhi < n)
                *(__half2*)&g_half[rhi * 128 + c] =
                    __floats2half2_rn(acc[mt][j][2] * dhi, acc[mt][j][3] * dhi);
        }
    }
}

// ---------------------------------------------------------------------------
// Aggregate (warp per node, fp16 gather, fp32 accumulate):
//   acc = g[i] + sum_{e in CSR row i} g[src_e];  h = relu(dinv_i*acc + b)
// FINAL=0: store h as fp16 to g_h2.  FINAL=1: fuse FC + log_softmax.
// ---------------------------------------------------------------------------
__device__ __forceinline__ void add_row(float4& acc, uint2 v) {
    float2 p0 = __half22float2(*(__half2*)&v.x);
    float2 p1 = __half22float2(*(__half2*)&v.y);
    acc.x += p0.x; acc.y += p0.y; acc.z += p1.x; acc.w += p1.y;
}

template <int FINAL>
__global__ void k_agg(const float* __restrict__ b,
                      const float* __restrict__ Wfc,
                      const float* __restrict__ bfc,
                      float* __restrict__ out,
                      int n) {
    int widx = (blockIdx.x * blockDim.x + threadIdx.x) >> 5;
    int q = threadIdx.x & 31;
    if (widx >= n) return;

    const uint2* gh = (const uint2*)g_half;
    int base = g_rowstart[widx];
    int end  = base + g_cnt[widx];

    float4 acc = make_float4(0.f, 0.f, 0.f, 0.f);
    add_row(acc, gh[widx * 32 + q]);          // self-loop term

    int e = base;
    for (; e + 4 <= end; e += 4) {
        int s0 = g_csr[e];
        int s1 = g_csr[e + 1];
        int s2 = g_csr[e + 2];
        int s3 = g_csr[e + 3];
        uint2 v0 = gh[s0 * 32 + q];
        uint2 v1 = gh[s1 * 32 + q];
        uint2 v2 = gh[s2 * 32 + q];
        uint2 v3 = gh[s3 * 32 + q];
        add_row(acc, v0); add_row(acc, v1);
        add_row(acc, v2); add_row(acc, v3);
    }
    for (; e < end; e++) add_row(acc, gh[g_csr[e] * 32 + q]);

    float dv = g_dinv[widx];
    float4 bb = ((const float4*)b)[q];
    float4 h;
    h.x = fmaxf(dv * acc.x + bb.x, 0.f);
    h.y = fmaxf(dv * acc.y + bb.y, 0.f);
    h.z = fmaxf(dv * acc.z + bb.z, 0.f);
    h.w = fmaxf(dv * acc.w + bb.w, 0.f);

    if (!FINAL) {
        uint2 st;
        *(__half2*)&st.x = __floats2half2_rn(h.x, h.y);
        *(__half2*)&st.y = __floats2half2_rn(h.z, h.w);
        ((uint2*)g_h2)[widx * 32 + q] = st;
    } else {
        const float4* w4 = (const float4*)Wfc;
        float4 w0 = w4[q * 2];
        float4 w1 = w4[q * 2 + 1];
        float l0 = h.x * w0.x + h.y * w0.z + h.z * w1.x + h.w * w1.z;
        float l1 = h.x * w0.y + h.y * w0.w + h.z * w1.y + h.w * w1.w;
#pragma unroll
        for (int o = 16; o > 0; o >>= 1) {
            l0 += __shfl_xor_sync(0xffffffffu, l0, o);
            l1 += __shfl_xor_sync(0xffffffffu, l1, o);
        }
        if (q == 0) {
            l0 += bfc[0];
            l1 += bfc[1];
            float m = fmaxf(l0, l1);
            float z = m + logf(expf(l0 - m) + expf(l1 - m));
            out[widx * 2]     = l0 - z;
            out[widx * 2 + 1] = l1 - z;
        }
    }
}

// ---------------------------------------------------------------------------
extern "C" void kernel_launch(void* const* d_in, const int* in_sizes, int n_in,
                              void* d_out, int out_size) {
    const float* x   = (const float*)d_in[0];
    const void*  ei  = d_in[1];
    const float* W1  = (const float*)d_in[2];
    const float* b1  = (const float*)d_in[3];
    const float* W2  = (const float*)d_in[4];
    const float* b2  = (const float*)d_in[5];
    const float* Wfc = (const float*)d_in[6];
    const float* bfc = (const float*)d_in[7];
    float*       out = (float*)d_out;

    int n = in_sizes[0] / FEAT;
    int E = in_sizes[1] / 2;

    int tb = 256;
    int node_blocks = (n + tb - 1) / tb;
    int edge_blocks = (E + tb - 1) / tb;
    int gemm_blocks = (n + 127) / 128;
    int warp_blocks = (int)(((long long)n * 32 + tb - 1) / tb);

    // 1-3: histogram + dinv
    k_init<<<node_blocks, tb>>>(ei, n);
    k_hist<<<edge_blocks, tb>>>(ei, E);
    k_dinv<<<node_blocks, tb>>>(n);

    // 4: layer-1 GEMM (profiled launch)
    k_gemm_f16<<<gemm_blocks, tb>>>(x, W1, n, 0);

    // 5-8: CSR finalize
    k_scan1<<<NBLK_SCAN, SCAN_B>>>(n);
    k_scan2<<<1, 512>>>();
    k_scan3<<<node_blocks, tb>>>(n);
    k_place<<<edge_blocks, tb>>>(ei, E);

    // 9: layer-1 aggregate
    k_agg<0><<<warp_blocks, tb>>>(b1, nullptr, nullptr, nullptr, n);

    // 10-11: layer 2 + fused FC/log_softmax
    k_gemm_f16<<<gemm_blocks, tb>>>(x, W2, n, 1);
    k_agg<1><<<warp_blocks, tb>>>(b2, Wfc, bfc, out, n);
}

// round 9
// speedup vs baseline: 1.7506x; 1.0676x over previous
#include <cuda_runtime.h>
#include <cuda_fp16.h>
#include <math.h>

#define NODES 100000
#define EDGES_MAX 1600000
#define FEAT  128
#define SCAN_B 256
#define NBLK_SCAN ((NODES + SCAN_B - 1) / SCAN_B)   // 391

// Scratch: __device__ globals (allocation-free rule). Device-side use only.
__device__ __half g_x2[NODES * FEAT];    // fp16 copy of input x
__device__ __half g_half[NODES * FEAT];  // g = (in @ W) * dinv  (agg gather src)
__device__ __half g_h2[NODES * FEAT];    // layer-1 output h (GEMM-2 input)
__device__ __half g_w1h[FEAT * FEAT];    // fp16 W1
__device__ __half g_w2h[FEAT * FEAT];    // fp16 W2
__device__ int    g_cnt[NODES];
__device__ int    g_incl[NODES];
__device__ int    g_rowstart[NODES];
__device__ int    g_cur[NODES];
__device__ int    g_poff[NBLK_SCAN + 1];
__device__ int    g_csr[EDGES_MAX];
__device__ int    g_idx64;

// ---------------------------------------------------------------------------
__global__ void k_init(const void* __restrict__ ei, int n) {
    int i = blockIdx.x * blockDim.x + threadIdx.x;
    if (i < n) g_cnt[i] = 0;
    if (blockIdx.x == 0) {
        __shared__ int ok;
        if (threadIdx.x == 0) ok = 1;
        __syncthreads();
        long long v = ((const long long*)ei)[threadIdx.x];
        if (v < 0 || v >= NODES) ok = 0;
        __syncthreads();
        if (threadIdx.x == 0) g_idx64 = ok;
    }
}

__device__ __forceinline__ int load_idx(const void* ei, long long elem) {
    if (g_idx64) return (int)((const long long*)ei)[elem];
    return ((const int*)ei)[elem];
}

// ---------------------------------------------------------------------------
__global__ void k_hist(const void* __restrict__ ei, int E) {
    int e = blockIdx.x * blockDim.x + threadIdx.x;
    if (e >= E) return;
    int d = load_idx(ei, (long long)E + e);
    if ((unsigned)d < NODES) atomicAdd(&g_cnt[d], 1);
}

// ---------------------------------------------------------------------------
// prep: convert x, W1, W2 to fp16 (4 fp32 -> 4 fp16 per thread).
// slots [0, n*32)           : x
// slots [n*32, n*32+4096)   : W1  (16384/4)
// slots [n*32+4096, +8192)  : W2
// ---------------------------------------------------------------------------
__global__ void k_prep(const float* __restrict__ x,
                       const float* __restrict__ W1,
                       const float* __restrict__ W2, int n) {
    int idx = blockIdx.x * blockDim.x + threadIdx.x;
    int nx = n * 32;
    const float4* src;
    uint2* dst;
    int off;
    if (idx < nx) {
        src = (const float4*)x;  dst = (uint2*)g_x2;  off = idx;
    } else if (idx < nx + 4096) {
        src = (const float4*)W1; dst = (uint2*)g_w1h; off = idx - nx;
    } else if (idx < nx + 8192) {
        src = (const float4*)W2; dst = (uint2*)g_w2h; off = idx - nx - 4096;
    } else return;
    float4 v = src[off];
    uint2 d;
    *(__half2*)&d.x = __floats2half2_rn(v.x, v.y);
    *(__half2*)&d.y = __floats2half2_rn(v.z, v.w);
    dst[off] = d;
}

// ---------------------------------------------------------------------------
// CSR scans + placement
// ---------------------------------------------------------------------------
__global__ void k_scan1(int n) {
    __shared__ int sm[SCAN_B];
    int i = blockIdx.x * SCAN_B + threadIdx.x;
    int v = (i < n) ? g_cnt[i] : 0;
    sm[threadIdx.x] = v;
    __syncthreads();
#pragma unroll
    for (int o = 1; o < SCAN_B; o <<= 1) {
        int t = (threadIdx.x >= o) ? sm[threadIdx.x - o] : 0;
        __syncthreads();
        sm[threadIdx.x] += t;
        __syncthreads();
    }
    if (i < n) g_incl[i] = sm[threadIdx.x];
    if (threadIdx.x == SCAN_B - 1) g_poff[blockIdx.x] = sm[SCAN_B - 1];
}

__global__ void k_scan2() {
    __shared__ int sm[512];
    int i = threadIdx.x;
    int v = (i < NBLK_SCAN) ? g_poff[i] : 0;
    sm[i] = v;
    __syncthreads();
#pragma unroll
    for (int o = 1; o < 512; o <<= 1) {
        int t = (i >= o) ? sm[i - o] : 0;
        __syncthreads();
        sm[i] += t;
        __syncthreads();
    }
    if (i < NBLK_SCAN) g_poff[i] = sm[i] - v;   // exclusive
}

__global__ void k_scan3(int n) {
    int i = blockIdx.x * blockDim.x + threadIdx.x;
    if (i >= n) return;
    int c = g_cnt[i];
    int rs = g_incl[i] - c + g_poff[i >> 8];
    g_rowstart[i] = rs;
    g_cur[i] = rs;
}

__global__ void k_place(const void* __restrict__ ei, int E) {
    int e = blockIdx.x * blockDim.x + threadIdx.x;
    if (e >= E) return;
    int s = load_idx(ei, e);
    int d = load_idx(ei, (long long)E + e);
    if ((unsigned)s >= NODES || (unsigned)d >= NODES) return;
    int pos = atomicAdd(&g_cur[d], 1);
    g_csr[pos] = s;
}

// ---------------------------------------------------------------------------
// fp16 GEMM, full-K single-stage, cp.async staging:
//   g_half[row][c] = fp16( (sum_k A[row][k] * W[k][c]) * rsqrt(cnt[row]+1) )
// BM=128, N=128, K=128. 8 warps (2x4), warp tile 64x32.
// Smem: As[128][136], Ws[128][136] halfs (dynamic, 69632 B).
// ---------------------------------------------------------------------------
#define SROW 136   // half stride (272 B): conflict-free ldmatrix

__global__ void __launch_bounds__(256)
k_gemm_f16(int n, int use_h) {
    extern __shared__ __half smem[];
    __half* As = smem;
    __half* Ws = smem + 128 * SROW;

    int tid  = threadIdx.x;
    int wid  = tid >> 5;
    int lane = tid & 31;
    int gq   = lane >> 2;
    int tq   = lane & 3;
    int warp_m = wid & 1;
    int warp_n = wid >> 1;
    int row0 = blockIdx.x * 128;

    const __half* Ag = use_h ? g_h2 : g_x2;
    const __half* Wg = use_h ? g_w2h : g_w1h;

    // ---- cp.async staging: A tile + full W, 16B per op, zero-fill OOB ----
#pragma unroll
    for (int i = 0; i < 8; i++) {
        int slot = tid + i * 256;           // 0..2047
        int r   = slot >> 4;                // 0..127
        int c16 = slot & 15;                // 16B chunk in row
        unsigned da = (unsigned)__cvta_generic_to_shared(&As[r * SROW + c16 * 8]);
        const __half* sa = Ag + (long long)(row0 + r) * 128 + c16 * 8;
        int va = (row0 + r < n) ? 16 : 0;
        asm volatile("cp.async.ca.shared.global [%0], [%1], 16, %2;"
                     :: "r"(da), "l"(sa), "r"(va));
        unsigned dw = (unsigned)__cvta_generic_to_shared(&Ws[r * SROW + c16 * 8]);
        const __half* sw = Wg + r * 128 + c16 * 8;
        asm volatile("cp.async.ca.shared.global [%0], [%1], 16;"
                     :: "r"(dw), "l"(sw));
    }
    asm volatile("cp.async.commit_group;");
    asm volatile("cp.async.wait_group 0;");
    __syncthreads();

    float acc[4][4][4];
#pragma unroll
    for (int mt = 0; mt < 4; mt++)
#pragma unroll
        for (int j = 0; j < 4; j++)
#pragma unroll
            for (int r = 0; r < 4; r++) acc[mt][j][r] = 0.f;

    unsigned a_base[4], b_base[2];
    {
        int arow = lane & 15;
        int akof = ((lane >> 4) & 1) * 8;
#pragma unroll
        for (int mt = 0; mt < 4; mt++)
            a_base[mt] = (unsigned)__cvta_generic_to_shared(
                &As[(warp_m * 64 + mt * 16 + arow) * SROW + akof]);
        int krow = lane & 15;
        int nof  = ((lane >> 4) & 1) * 8;
#pragma unroll
        for (int nt2 = 0; nt2 < 2; nt2++)
            b_base[nt2] = (unsigned)__cvta_generic_to_shared(
                &Ws[krow * SROW + warp_n * 32 + nt2 * 16 + nof]);
    }

#pragma unroll
    for (int ks = 0; ks < 8; ks++) {
        unsigned a[4][4];
#pragma unroll
        for (int mt = 0; mt < 4; mt++) {
            asm volatile(
                "ldmatrix.sync.aligned.m8n8.x4.shared.b16 {%0,%1,%2,%3}, [%4];"
                : "=r"(a[mt][0]), "=r"(a[mt][1]), "=r"(a[mt][2]), "=r"(a[mt][3])
                : "r"(a_base[mt] + ks * 32));            // +16 halfs in k
        }
        unsigned b[2][4];
#pragma unroll
        for (int nt2 = 0; nt2 < 2; nt2++) {
            asm volatile(
                "ldmatrix.sync.aligned.m8n8.x4.trans.shared.b16 {%0,%1,%2,%3}, [%4];"
                : "=r"(b[nt2][0]), "=r"(b[nt2][1]), "=r"(b[nt2][2]), "=r"(b[nt2][3])
                : "r"(b_base[nt2] + ks * 16 * SROW * 2)); // +16 k-rows
        }
#pragma unroll
        for (int nt2 = 0; nt2 < 2; nt2++) {
#pragma unroll
            for (int h8 = 0; h8 < 2; h8++) {
                int j = nt2 * 2 + h8;
#pragma unroll
                for (int mt = 0; mt < 4; mt++) {
                    asm volatile(
                        "mma.sync.aligned.m16n8k16.row.col.f32.f16.f16.f32 "
                        "{%0,%1,%2,%3}, {%4,%5,%6,%7}, {%8,%9}, {%0,%1,%2,%3};"
                        : "+f"(acc[mt][j][0]), "+f"(acc[mt][j][1]),
                          "+f"(acc[mt][j][2]), "+f"(acc[mt][j][3])
                        : "r"(a[mt][0]), "r"(a[mt][1]),
                          "r"(a[mt][2]), "r"(a[mt][3]),
                          "r"(b[nt2][h8 * 2]), "r"(b[nt2][h8 * 2 + 1]));
                }
            }
        }
    }

    // epilogue: dinv = rsqrt(cnt+1), convert to fp16, write g_half
#pragma unroll
    for (int mt = 0; mt < 4; mt++) {
        int rlo = row0 + warp_m * 64 + mt * 16 + gq;
        int rhi = rlo + 8;
        float dlo = (rlo < n) ? rsqrtf((float)g_cnt[rlo] + 1.0f) : 0.f;
        float dhi = (rhi < n) ? rsqrtf((float)g_cnt[rhi] + 1.0f) : 0.f;
#pragma unroll
        for (int j = 0; j < 4; j++) {
            int c = warp_n * 32 + j * 8 + 2 * tq;
            if (rlo < n)
                *(__half2*)&g_half[rlo * 128 + c] =
                    __floats2half2_rn(acc[mt][j][0] * dlo, acc[mt][j][1] * dlo);
            if (rhi < n)
                *(__half2*)&g_half[rhi * 128 + c] =
                    __floats2half2_rn(acc[mt][j][2] * dhi, acc[mt][j][3] * dhi);
        }
    }
}

// ---------------------------------------------------------------------------
// Aggregate (warp per node, fp16 gather, fp32 accumulate).
// ---------------------------------------------------------------------------
__device__ __forceinline__ void add_row(float4& acc, uint2 v) {
    float2 p0 = __half22float2(*(__half2*)&v.x);
    float2 p1 = __half22float2(*(__half2*)&v.y);
    acc.x += p0.x; acc.y += p0.y; acc.z += p1.x; acc.w += p1.y;
}

template <int FINAL>
__global__ void k_agg(const float* __restrict__ b,
                      const float* __restrict__ Wfc,
                      const float* __restrict__ bfc,
                      float* __restrict__ out,
                      int n) {
    int widx = (blockIdx.x * blockDim.x + threadIdx.x) >> 5;
    int q = threadIdx.x & 31;
    if (widx >= n) return;

    const uint2* gh = (const uint2*)g_half;
    int base = g_rowstart[widx];
    int cnt  = g_cnt[widx];
    int end  = base + cnt;

    float4 acc = make_float4(0.f, 0.f, 0.f, 0.f);
    add_row(acc, gh[widx * 32 + q]);          // self-loop term

    int e = base;
    for (; e + 4 <= end; e += 4) {
        int s0 = g_csr[e];
        int s1 = g_csr[e + 1];
        int s2 = g_csr[e + 2];
        int s3 = g_csr[e + 3];
        uint2 v0 = gh[s0 * 32 + q];
        uint2 v1 = gh[s1 * 32 + q];
        uint2 v2 = gh[s2 * 32 + q];
        uint2 v3 = gh[s3 * 32 + q];
        add_row(acc, v0); add_row(acc, v1);
        add_row(acc, v2); add_row(acc, v3);
    }
    for (; e < end; e++) add_row(acc, gh[g_csr[e] * 32 + q]);

    float dv = rsqrtf((float)cnt + 1.0f);
    float4 bb = ((const float4*)b)[q];
    float4 h;
    h.x = fmaxf(dv * acc.x + bb.x, 0.f);
    h.y = fmaxf(dv * acc.y + bb.y, 0.f);
    h.z = fmaxf(dv * acc.z + bb.z, 0.f);
    h.w = fmaxf(dv * acc.w + bb.w, 0.f);

    if (!FINAL) {
        uint2 st;
        *(__half2*)&st.x = __floats2half2_rn(h.x, h.y);
        *(__half2*)&st.y = __floats2half2_rn(h.z, h.w);
        ((uint2*)g_h2)[widx * 32 + q] = st;
    } else {
        const float4* w4 = (const float4*)Wfc;
        float4 w0 = w4[q * 2];
        float4 w1 = w4[q * 2 + 1];
        float l0 = h.x * w0.x + h.y * w0.z + h.z * w1.x + h.w * w1.z;
        float l1 = h.x * w0.y + h.y * w0.w + h.z * w1.y + h.w * w1.w;
#pragma unroll
        for (int o = 16; o > 0; o >>= 1) {
            l0 += __shfl_xor_sync(0xffffffffu, l0, o);
            l1 += __shfl_xor_sync(0xffffffffu, l1, o);
        }
        if (q == 0) {
            l0 += bfc[0];
            l1 += bfc[1];
            float m = fmaxf(l0, l1);
            float z = m + logf(expf(l0 - m) + expf(l1 - m));
            out[widx * 2]     = l0 - z;
            out[widx * 2 + 1] = l1 - z;
        }
    }
}

// ---------------------------------------------------------------------------
extern "C" void kernel_launch(void* const* d_in, const int* in_sizes, int n_in,
                              void* d_out, int out_size) {
    const float* x   = (const float*)d_in[0];
    const void*  ei  = d_in[1];
    const float* W1  = (const float*)d_in[2];
    const float* b1  = (const float*)d_in[3];
    const float* W2  = (const float*)d_in[4];
    const float* b2  = (const float*)d_in[5];
    const float* Wfc = (const float*)d_in[6];
    const float* bfc = (const float*)d_in[7];
    float*       out = (float*)d_out;

    int n = in_sizes[0] / FEAT;
    int E = in_sizes[1] / 2;

    int tb = 256;
    int node_blocks = (n + tb - 1) / tb;
    int edge_blocks = (E + tb - 1) / tb;
    int gemm_blocks = (n + 127) / 128;
    int warp_blocks = (int)(((long long)n * 32 + tb - 1) / tb);
    int prep_blocks = (n * 32 + 8192 + tb - 1) / tb;

    static int smem_set = 0;
    int gemm_smem = 2 * 128 * SROW * (int)sizeof(__half);   // 69632
    if (!smem_set) {
        cudaFuncSetAttribute(k_gemm_f16,
                             cudaFuncAttributeMaxDynamicSharedMemorySize, gemm_smem);
        smem_set = 1;
    }

    // 1-3: histogram + fp16 conversion
    k_init<<<node_blocks, tb>>>(ei, n);
    k_hist<<<edge_blocks, tb>>>(ei, E);
    k_prep<<<prep_blocks, tb>>>(x, W1, W2, n);

    // 4: layer-1 GEMM (profiled launch)
    k_gemm_f16<<<gemm_blocks, tb, gemm_smem>>>(n, 0);

    // 5-8: CSR finalize
    k_scan1<<<NBLK_SCAN, SCAN_B>>>(n);
    k_scan2<<<1, 512>>>();
    k_scan3<<<node_blocks, tb>>>(n);
    k_place<<<edge_blocks, tb>>>(ei, E);

    // 9: layer-1 aggregate
    k_agg<0><<<warp_blocks, tb>>>(b1, nullptr, nullptr, nullptr, n);

    // 10-11: layer 2 + fused FC/log_softmax
    k_gemm_f16<<<gemm_blocks, tb, gemm_smem>>>(n, 1);
    k_agg<1><<<warp_blocks, tb>>>(b2, Wfc, bfc, out, n);
}

// round 10
// speedup vs baseline: 1.8613x; 1.0633x over previous
#include <cuda_runtime.h>
#include <cuda_fp16.h>
#include <math.h>

#define NODES 100000
#define EDGES_MAX 1600000
#define FEAT  128
#define SCAN_B 256
#define NBLK_SCAN ((NODES + SCAN_B - 1) / SCAN_B)   // 391

// Scratch: __device__ globals (allocation-free rule). Device-side use only.
__device__ __half g_half[NODES * FEAT];  // g = (in @ W) * dinv  (agg gather src)
__device__ __half g_h2[NODES * FEAT];    // layer-1 output h (GEMM-2 input)
__device__ __half g_w1h[FEAT * FEAT];    // fp16 W1
__device__ __half g_w2h[FEAT * FEAT];    // fp16 W2
__device__ int    g_cnt[NODES];
__device__ int    g_incl[NODES];
__device__ int    g_rowstart[NODES];
__device__ int    g_cur[NODES];
__device__ int    g_poff[NBLK_SCAN + 1];
__device__ int    g_csr[EDGES_MAX];
__device__ int    g_idx64;

// ---------------------------------------------------------------------------
__global__ void k_init(const void* __restrict__ ei, int n) {
    int i = blockIdx.x * blockDim.x + threadIdx.x;
    if (i < n) g_cnt[i] = 0;
    if (blockIdx.x == 0) {
        __shared__ int ok;
        if (threadIdx.x == 0) ok = 1;
        __syncthreads();
        long long v = ((const long long*)ei)[threadIdx.x];
        if (v < 0 || v >= NODES) ok = 0;
        __syncthreads();
        if (threadIdx.x == 0) g_idx64 = ok;
    }
}

__device__ __forceinline__ int load_idx(const void* ei, long long elem) {
    if (g_idx64) return (int)((const long long*)ei)[elem];
    return ((const int*)ei)[elem];
}

// ---------------------------------------------------------------------------
__global__ void k_hist(const void* __restrict__ ei, int E) {
    int e = blockIdx.x * blockDim.x + threadIdx.x;
    if (e >= E) return;
    int d = load_idx(ei, (long long)E + e);
    if ((unsigned)d < NODES) atomicAdd(&g_cnt[d], 1);
}

// ---------------------------------------------------------------------------
// prep: convert W1, W2 to fp16 (x conversion is fused into GEMM-1 staging).
// ---------------------------------------------------------------------------
__global__ void k_prep(const float* __restrict__ W1,
                       const float* __restrict__ W2) {
    int idx = blockIdx.x * blockDim.x + threadIdx.x;
    const float4* src;
    uint2* dst;
    int off;
    if (idx < 4096) {
        src = (const float4*)W1; dst = (uint2*)g_w1h; off = idx;
    } else if (idx < 8192) {
        src = (const float4*)W2; dst = (uint2*)g_w2h; off = idx - 4096;
    } else return;
    float4 v = src[off];
    uint2 d;
    *(__half2*)&d.x = __floats2half2_rn(v.x, v.y);
    *(__half2*)&d.y = __floats2half2_rn(v.z, v.w);
    dst[off] = d;
}

// ---------------------------------------------------------------------------
// CSR scans + placement
// ---------------------------------------------------------------------------
__global__ void k_scan1(int n) {
    __shared__ int sm[SCAN_B];
    int i = blockIdx.x * SCAN_B + threadIdx.x;
    int v = (i < n) ? g_cnt[i] : 0;
    sm[threadIdx.x] = v;
    __syncthreads();
#pragma unroll
    for (int o = 1; o < SCAN_B; o <<= 1) {
        int t = (threadIdx.x >= o) ? sm[threadIdx.x - o] : 0;
        __syncthreads();
        sm[threadIdx.x] += t;
        __syncthreads();
    }
    if (i < n) g_incl[i] = sm[threadIdx.x];
    if (threadIdx.x == SCAN_B - 1) g_poff[blockIdx.x] = sm[SCAN_B - 1];
}

__global__ void k_scan2() {
    __shared__ int sm[512];
    int i = threadIdx.x;
    int v = (i < NBLK_SCAN) ? g_poff[i] : 0;
    sm[i] = v;
    __syncthreads();
#pragma unroll
    for (int o = 1; o < 512; o <<= 1) {
        int t = (i >= o) ? sm[i - o] : 0;
        __syncthreads();
        sm[i] += t;
        __syncthreads();
    }
    if (i < NBLK_SCAN) g_poff[i] = sm[i] - v;   // exclusive
}

__global__ void k_scan3(int n) {
    int i = blockIdx.x * blockDim.x + threadIdx.x;
    if (i >= n) return;
    int c = g_cnt[i];
    int rs = g_incl[i] - c + g_poff[i >> 8];
    g_rowstart[i] = rs;
    g_cur[i] = rs;
}

__global__ void k_place(const void* __restrict__ ei, int E) {
    int e = blockIdx.x * blockDim.x + threadIdx.x;
    if (e >= E) return;
    int s = load_idx(ei, e);
    int d = load_idx(ei, (long long)E + e);
    if ((unsigned)s >= NODES || (unsigned)d >= NODES) return;
    int pos = atomicAdd(&g_cur[d], 1);
    g_csr[pos] = s;
}

// ---------------------------------------------------------------------------
// fp16 GEMM, full-K single tile:
//   g_half[row][c] = fp16( (sum_k A[row][k] * W[k][c]) * rsqrt(cnt[row]+1) )
// BM=128, N=128, K=128. 8 warps (2x4), warp tile 64x32.
// Layer 1 (use_h=0): A staged from fp32 x via LDG+cvt+STS; W via cp.async.
// Layer 2 (use_h=1): A,W via cp.async in two commit groups (k-split),
//                    compute of first k-half overlaps second half's loads.
// Smem: As[128][136], Ws[128][136] halfs (dynamic, 69632 B).
// ---------------------------------------------------------------------------
#define SROW 136   // half stride (272 B): conflict-free ldmatrix

__global__ void __launch_bounds__(256)
k_gemm_f16(const float* __restrict__ x, int n, int use_h) {
    extern __shared__ __half smem[];
    __half* As = smem;
    __half* Ws = smem + 128 * SROW;

    int tid  = threadIdx.x;
    int wid  = tid >> 5;
    int lane = tid & 31;
    int gq   = lane >> 2;
    int tq   = lane & 3;
    int warp_m = wid & 1;
    int warp_n = wid >> 1;
    int row0 = blockIdx.x * 128;

    const __half* Wg = use_h ? g_w2h : g_w1h;

    float acc[4][4][4];
#pragma unroll
    for (int mt = 0; mt < 4; mt++)
#pragma unroll
        for (int j = 0; j < 4; j++)
#pragma unroll
            for (int r = 0; r < 4; r++) acc[mt][j][r] = 0.f;

    unsigned a_base[4], b_base[2];
    {
        int arow = lane & 15;
        int akof = ((lane >> 4) & 1) * 8;
#pragma unroll
        for (int mt = 0; mt < 4; mt++)
            a_base[mt] = (unsigned)__cvta_generic_to_shared(
                &As[(warp_m * 64 + mt * 16 + arow) * SROW + akof]);
        int krow = lane & 15;
        int nof  = ((lane >> 4) & 1) * 8;
#pragma unroll
        for (int nt2 = 0; nt2 < 2; nt2++)
            b_base[nt2] = (unsigned)__cvta_generic_to_shared(
                &Ws[krow * SROW + warp_n * 32 + nt2 * 16 + nof]);
    }

    if (!use_h) {
        // ---- W via cp.async (all of it), A from fp32 x via LDG+cvt+STS ----
#pragma unroll
        for (int i = 0; i < 8; i++) {
            int slot = tid + i * 256;           // 0..2047
            int r   = slot >> 4;
            int c16 = slot & 15;
            unsigned dw = (unsigned)__cvta_generic_to_shared(&Ws[r * SROW + c16 * 8]);
            asm volatile("cp.async.ca.shared.global [%0], [%1], 16;"
                         :: "r"(dw), "l"(Wg + r * 128 + c16 * 8));
        }
        asm volatile("cp.async.commit_group;");

        const float4* X4 = (const float4*)x;
#pragma unroll
        for (int i = 0; i < 8; i++) {
            int slot = tid + i * 256;
            int r   = slot >> 4;
            int c16 = slot & 15;
            int gr = row0 + r;
            float4 v0 = make_float4(0.f, 0.f, 0.f, 0.f);
            float4 v1 = v0;
            if (gr < n) {
                v0 = X4[(long long)gr * 32 + c16 * 2];
                v1 = X4[(long long)gr * 32 + c16 * 2 + 1];
            }
            uint4 d;
            *(__half2*)&d.x = __floats2half2_rn(v0.x, v0.y);
            *(__half2*)&d.y = __floats2half2_rn(v0.z, v0.w);
            *(__half2*)&d.z = __floats2half2_rn(v1.x, v1.y);
            *(__half2*)&d.w = __floats2half2_rn(v1.z, v1.w);
            *(uint4*)&As[r * SROW + c16 * 8] = d;
        }
        asm volatile("cp.async.wait_group 0;");
        __syncthreads();

#pragma unroll
        for (int ks = 0; ks < 8; ks++) {
            unsigned a[4][4], b[2][4];
#pragma unroll
            for (int mt = 0; mt < 4; mt++)
                asm volatile(
                    "ldmatrix.sync.aligned.m8n8.x4.shared.b16 {%0,%1,%2,%3}, [%4];"
                    : "=r"(a[mt][0]), "=r"(a[mt][1]), "=r"(a[mt][2]), "=r"(a[mt][3])
                    : "r"(a_base[mt] + ks * 32));
#pragma unroll
            for (int nt2 = 0; nt2 < 2; nt2++)
                asm volatile(
                    "ldmatrix.sync.aligned.m8n8.x4.trans.shared.b16 {%0,%1,%2,%3}, [%4];"
                    : "=r"(b[nt2][0]), "=r"(b[nt2][1]), "=r"(b[nt2][2]), "=r"(b[nt2][3])
                    : "r"(b_base[nt2] + ks * 16 * SROW * 2));
#pragma unroll
            for (int nt2 = 0; nt2 < 2; nt2++)
#pragma unroll
                for (int h8 = 0; h8 < 2; h8++) {
                    int j = nt2 * 2 + h8;
#pragma unroll
                    for (int mt = 0; mt < 4; mt++)
                        asm volatile(
                            "mma.sync.aligned.m16n8k16.row.col.f32.f16.f16.f32 "
                            "{%0,%1,%2,%3}, {%4,%5,%6,%7}, {%8,%9}, {%0,%1,%2,%3};"
                            : "+f"(acc[mt][j][0]), "+f"(acc[mt][j][1]),
                              "+f"(acc[mt][j][2]), "+f"(acc[mt][j][3])
                            : "r"(a[mt][0]), "r"(a[mt][1]),
                              "r"(a[mt][2]), "r"(a[mt][3]),
                              "r"(b[nt2][h8 * 2]), "r"(b[nt2][h8 * 2 + 1]));
                }
        }
    } else {
        // ---- both via cp.async, two k-split commit groups ----
        const __half* Ag = g_h2;
#pragma unroll
        for (int grp = 0; grp < 2; grp++) {
#pragma unroll
            for (int i = 0; i < 4; i++) {
                int slot = tid + i * 256;       // 0..1023
                int r   = slot >> 3;            // 0..127
                int c16 = (slot & 7) + grp * 8; // k-chunks 0-7 / 8-15
                unsigned da = (unsigned)__cvta_generic_to_shared(&As[r * SROW + c16 * 8]);
                const __half* sa = Ag + (long long)(row0 + r) * 128 + c16 * 8;
                int va = (row0 + r < n) ? 16 : 0;
                asm volatile("cp.async.ca.shared.global [%0], [%1], 16, %2;"
                             :: "r"(da), "l"(sa), "r"(va));
                int wr  = (slot >> 3) & 63;     // 0..63
                int wr2 = grp * 64 + wr;        // W k-rows 0-63 / 64-127
                int wc16 = slot & 7;            // reuse slot bits: 1024 slots = 64 rows x 16 chunks
                int wrow = grp * 64 + (slot >> 4);   // 0..63 per group
                int wchk = slot & 15;
                unsigned dw = (unsigned)__cvta_generic_to_shared(&Ws[wrow * SROW + wchk * 8]);
                asm volatile("cp.async.ca.shared.global [%0], [%1], 16;"
                             :: "r"(dw), "l"(Wg + wrow * 128 + wchk * 8));
                (void)wr2; (void)wc16;
            }
            asm volatile("cp.async.commit_group;");
        }

        asm volatile("cp.async.wait_group 1;");
        __syncthreads();
#pragma unroll
        for (int ks = 0; ks < 4; ks++) {
            unsigned a[4][4], b[2][4];
#pragma unroll
            for (int mt = 0; mt < 4; mt++)
                asm volatile(
                    "ldmatrix.sync.aligned.m8n8.x4.shared.b16 {%0,%1,%2,%3}, [%4];"
                    : "=r"(a[mt][0]), "=r"(a[mt][1]), "=r"(a[mt][2]), "=r"(a[mt][3])
                    : "r"(a_base[mt] + ks * 32));
#pragma unroll
            for (int nt2 = 0; nt2 < 2; nt2++)
                asm volatile(
                    "ldmatrix.sync.aligned.m8n8.x4.trans.shared.b16 {%0,%1,%2,%3}, [%4];"
                    : "=r"(b[nt2][0]), "=r"(b[nt2][1]), "=r"(b[nt2][2]), "=r"(b[nt2][3])
                    : "r"(b_base[nt2] + ks * 16 * SROW * 2));
#pragma unroll
            for (int nt2 = 0; nt2 < 2; nt2++)
#pragma unroll
                for (int h8 = 0; h8 < 2; h8++) {
                    int j = nt2 * 2 + h8;
#pragma unroll
                    for (int mt = 0; mt < 4; mt++)
                        asm volatile(
                            "mma.sync.aligned.m16n8k16.row.col.f32.f16.f16.f32 "
                            "{%0,%1,%2,%3}, {%4,%5,%6,%7}, {%8,%9}, {%0,%1,%2,%3};"
                            : "+f"(acc[mt][j][0]), "+f"(acc[mt][j][1]),
                              "+f"(acc[mt][j][2]), "+f"(acc[mt][j][3])
                            : "r"(a[mt][0]), "r"(a[mt][1]),
                              "r"(a[mt][2]), "r"(a[mt][3]),
                              "r"(b[nt2][h8 * 2]), "r"(b[nt2][h8 * 2 + 1]));
                }
        }
        asm volatile("cp.async.wait_group 0;");
        __syncthreads();
#pragma unroll
        for (int ks = 4; ks < 8; ks++) {
            unsigned a[4][4], b[2][4];
#pragma unroll
            for (int mt = 0; mt < 4; mt++)
                asm volatile(
                    "ldmatrix.sync.aligned.m8n8.x4.shared.b16 {%0,%1,%2,%3}, [%4];"
                    : "=r"(a[mt][0]), "=r"(a[mt][1]), "=r"(a[mt][2]), "=r"(a[mt][3])
                    : "r"(a_base[mt] + ks * 32));
#pragma unroll
            for (int nt2 = 0; nt2 < 2; nt2++)
                asm volatile(
                    "ldmatrix.sync.aligned.m8n8.x4.trans.shared.b16 {%0,%1,%2,%3}, [%4];"
                    : "=r"(b[nt2][0]), "=r"(b[nt2][1]), "=r"(b[nt2][2]), "=r"(b[nt2][3])
                    : "r"(b_base[nt2] + ks * 16 * SROW * 2));
#pragma unroll
            for (int nt2 = 0; nt2 < 2; nt2++)
#pragma unroll
                for (int h8 = 0; h8 < 2; h8++) {
                    int j = nt2 * 2 + h8;
#pragma unroll
                    for (int mt = 0; mt < 4; mt++)
                        asm volatile(
                            "mma.sync.aligned.m16n8k16.row.col.f32.f16.f16.f32 "
                            "{%0,%1,%2,%3}, {%4,%5,%6,%7}, {%8,%9}, {%0,%1,%2,%3};"
                            : "+f"(acc[mt][j][0]), "+f"(acc[mt][j][1]),
                              "+f"(acc[mt][j][2]), "+f"(acc[mt][j][3])
                            : "r"(a[mt][0]), "r"(a[mt][1]),
                              "r"(a[mt][2]), "r"(a[mt][3]),
                              "r"(b[nt2][h8 * 2]), "r"(b[nt2][h8 * 2 + 1]));
                }
        }
    }

    // epilogue: dinv = rsqrt(cnt+1), convert to fp16, write g_half
#pragma unroll
    for (int mt = 0; mt < 4; mt++) {
        int rlo = row0 + warp_m * 64 + mt * 16 + gq;
        int rhi = rlo + 8;
        float dlo = (rlo < n) ? rsqrtf((float)g_cnt[rlo] + 1.0f) : 0.f;
        float dhi = (rhi < n) ? rsqrtf((float)g_cnt[rhi] + 1.0f) : 0.f;
#pragma unroll
        for (int j = 0; j < 4; j++) {
            int c = warp_n * 32 + j * 8 + 2 * tq;
            if (rlo < n)
                *(__half2*)&g_half[rlo * 128 + c] =
                    __floats2half2_rn(acc[mt][j][0] * dlo, acc[mt][j][1] * dlo);
            if (rhi < n)
                *(__half2*)&g_half[rhi * 128 + c] =
                    __floats2half2_rn(acc[mt][j][2] * dhi, acc[mt][j][3] * dhi);
        }
    }
}

// ---------------------------------------------------------------------------
// Aggregate (warp per node, fp16 gather, fp32 accumulate, unroll x8).
// ---------------------------------------------------------------------------
__device__ __forceinline__ void add_row(float4& acc, uint2 v) {
    float2 p0 = __half22float2(*(__half2*)&v.x);
    float2 p1 = __half22float2(*(__half2*)&v.y);
    acc.x += p0.x; acc.y += p0.y; acc.z += p1.x; acc.w += p1.y;
}

template <int FINAL>
__global__ void k_agg(const float* __restrict__ b,
                      const float* __restrict__ Wfc,
                      const float* __restrict__ bfc,
                      float* __restrict__ out,
                      int n) {
    int widx = (blockIdx.x * blockDim.x + threadIdx.x) >> 5;
    int q = threadIdx.x & 31;
    if (widx >= n) return;

    const uint2* gh = (const uint2*)g_half;
    int base = g_rowstart[widx];
    int cnt  = g_cnt[widx];
    int end  = base + cnt;

    float4 acc = make_float4(0.f, 0.f, 0.f, 0.f);
    add_row(acc, gh[widx * 32 + q]);          // self-loop term

    int e = base;
    for (; e + 8 <= end; e += 8) {
        uint2 v0 = gh[g_csr[e]     * 32 + q];
        uint2 v1 = gh[g_csr[e + 1] * 32 + q];
        uint2 v2 = gh[g_csr[e + 2] * 32 + q];
        uint2 v3 = gh[g_csr[e + 3] * 32 + q];
        uint2 v4 = gh[g_csr[e + 4] * 32 + q];
        uint2 v5 = gh[g_csr[e + 5] * 32 + q];
        uint2 v6 = gh[g_csr[e + 6] * 32 + q];
        uint2 v7 = gh[g_csr[e + 7] * 32 + q];
        add_row(acc, v0); add_row(acc, v1); add_row(acc, v2); add_row(acc, v3);
        add_row(acc, v4); add_row(acc, v5); add_row(acc, v6); add_row(acc, v7);
    }
    for (; e + 2 <= end; e += 2) {
        uint2 v0 = gh[g_csr[e]     * 32 + q];
        uint2 v1 = gh[g_csr[e + 1] * 32 + q];
        add_row(acc, v0); add_row(acc, v1);
    }
    if (e < end) add_row(acc, gh[g_csr[e] * 32 + q]);

    float dv = rsqrtf((float)cnt + 1.0f);
    float4 bb = ((const float4*)b)[q];
    float4 h;
    h.x = fmaxf(dv * acc.x + bb.x, 0.f);
    h.y = fmaxf(dv * acc.y + bb.y, 0.f);
    h.z = fmaxf(dv * acc.z + bb.z, 0.f);
    h.w = fmaxf(dv * acc.w + bb.w, 0.f);

    if (!FINAL) {
        uint2 st;
        *(__half2*)&st.x = __floats2half2_rn(h.x, h.y);
        *(__half2*)&st.y = __floats2half2_rn(h.z, h.w);
        ((uint2*)g_h2)[widx * 32 + q] = st;
    } else {
        const float4* w4 = (const float4*)Wfc;
        float4 w0 = w4[q * 2];
        float4 w1 = w4[q * 2 + 1];
        float l0 = h.x * w0.x + h.y * w0.z + h.z * w1.x + h.w * w1.z;
        float l1 = h.x * w0.y + h.y * w0.w + h.z * w1.y + h.w * w1.w;
#pragma unroll
        for (int o = 16; o > 0; o >>= 1) {
            l0 += __shfl_xor_sync(0xffffffffu, l0, o);
            l1 += __shfl_xor_sync(0xffffffffu, l1, o);
        }
        if (q == 0) {
            l0 += bfc[0];
            l1 += bfc[1];
            float m = fmaxf(l0, l1);
            float z = m + logf(expf(l0 - m) + expf(l1 - m));
            out[widx * 2]     = l0 - z;
            out[widx * 2 + 1] = l1 - z;
        }
    }
}

// ---------------------------------------------------------------------------
extern "C" void kernel_launch(void* const* d_in, const int* in_sizes, int n_in,
                              void* d_out, int out_size) {
    const float* x   = (const float*)d_in[0];
    const void*  ei  = d_in[1];
    const float* W1  = (const float*)d_in[2];
    const float* b1  = (const float*)d_in[3];
    const float* W2  = (const float*)d_in[4];
    const float* b2  = (const float*)d_in[5];
    const float* Wfc = (const float*)d_in[6];
    const float* bfc = (const float*)d_in[7];
    float*       out = (float*)d_out;

    int n = in_sizes[0] / FEAT;
    int E = in_sizes[1] / 2;

    int tb = 256;
    int node_blocks = (n + tb - 1) / tb;
    int edge_blocks = (E + tb - 1) / tb;
    int gemm_blocks = (n + 127) / 128;
    int warp_blocks = (int)(((long long)n * 32 + tb - 1) / tb);

    static int smem_set = 0;
    int gemm_smem = 2 * 128 * SROW * (int)sizeof(__half);   // 69632
    if (!smem_set) {
        cudaFuncSetAttribute(k_gemm_f16,
                             cudaFuncAttributeMaxDynamicSharedMemorySize, gemm_smem);
        smem_set = 1;
    }

    // 1-3: histogram + W fp16 conversion
    k_init<<<node_blocks, tb>>>(ei, n);
    k_hist<<<edge_blocks, tb>>>(ei, E);
    k_prep<<<32, tb>>>(W1, W2);

    // 4: layer-1 GEMM (profiled launch; stages x fp32 -> fp16 itself)
    k_gemm_f16<<<gemm_blocks, tb, gemm_smem>>>(x, n, 0);

    // 5-8: CSR finalize
    k_scan1<<<NBLK_SCAN, SCAN_B>>>(n);
    k_scan2<<<1, 512>>>();
    k_scan3<<<node_blocks, tb>>>(n);
    k_place<<<edge_blocks, tb>>>(ei, E);

    // 9: layer-1 aggregate
    k_agg<0><<<warp_blocks, tb>>>(b1, nullptr, nullptr, nullptr, n);

    // 10-11: layer 2 + fused FC/log_softmax
    k_gemm_f16<<<gemm_blocks, tb, gemm_smem>>>(x, n, 1);
    k_agg<1><<<warp_blocks, tb>>>(b2, Wfc, bfc, out, n);
}

// round 11
// speedup vs baseline: 1.9581x; 1.0520x over previous
#include <cuda_runtime.h>
#include <cuda_fp16.h>
#include <math.h>

#define NODES 100000
#define EDGES_MAX 1600000
#define FEAT  128
#define SCAN_B 256
#define NBLK_SCAN ((NODES + SCAN_B - 1) / SCAN_B)   // 391

// Scratch: __device__ globals (allocation-free rule). Device-side use only.
__device__ __half g_half[NODES * FEAT];  // g = (in @ W) * dinv  (agg gather src)
__device__ __half g_h2[NODES * FEAT];    // layer-1 output h (GEMM-2 input)
__device__ __half g_w1h[FEAT * FEAT];    // fp16 W1
__device__ __half g_w2h[FEAT * FEAT];    // fp16 W2
__device__ int    g_cnt[NODES];
__device__ int    g_incl[NODES];
__device__ int    g_rowstart[NODES];
__device__ int    g_cur[NODES];
__device__ int    g_poff[NBLK_SCAN + 1];
__device__ int    g_csr[EDGES_MAX];
__device__ int    g_idx64;

// ---------------------------------------------------------------------------
__global__ void k_init(const void* __restrict__ ei, int n) {
    int i = blockIdx.x * blockDim.x + threadIdx.x;
    if (i < n) g_cnt[i] = 0;
    if (blockIdx.x == 0) {
        __shared__ int ok;
        if (threadIdx.x == 0) ok = 1;
        __syncthreads();
        long long v = ((const long long*)ei)[threadIdx.x];
        if (v < 0 || v >= NODES) ok = 0;
        __syncthreads();
        if (threadIdx.x == 0) g_idx64 = ok;
    }
}

__device__ __forceinline__ int load_idx(const void* ei, long long elem) {
    if (g_idx64) return (int)((const long long*)ei)[elem];
    return ((const int*)ei)[elem];
}

// ---------------------------------------------------------------------------
__global__ void k_hist(const void* __restrict__ ei, int E) {
    int e = blockIdx.x * blockDim.x + threadIdx.x;
    if (e >= E) return;
    int d = load_idx(ei, (long long)E + e);
    if ((unsigned)d < NODES) atomicAdd(&g_cnt[d], 1);
}

// ---------------------------------------------------------------------------
// prep: convert W1, W2 to fp16 (x conversion fused into GEMM-1 staging).
// ---------------------------------------------------------------------------
__global__ void k_prep(const float* __restrict__ W1,
                       const float* __restrict__ W2) {
    int idx = blockIdx.x * blockDim.x + threadIdx.x;
    const float4* src;
    uint2* dst;
    int off;
    if (idx < 4096) {
        src = (const float4*)W1; dst = (uint2*)g_w1h; off = idx;
    } else if (idx < 8192) {
        src = (const float4*)W2; dst = (uint2*)g_w2h; off = idx - 4096;
    } else return;
    float4 v = src[off];
    uint2 d;
    *(__half2*)&d.x = __floats2half2_rn(v.x, v.y);
    *(__half2*)&d.y = __floats2half2_rn(v.z, v.w);
    dst[off] = d;
}

// ---------------------------------------------------------------------------
// CSR scans + placement
// ---------------------------------------------------------------------------
__global__ void k_scan1(int n) {
    __shared__ int sm[SCAN_B];
    int i = blockIdx.x * SCAN_B + threadIdx.x;
    int v = (i < n) ? g_cnt[i] : 0;
    sm[threadIdx.x] = v;
    __syncthreads();
#pragma unroll
    for (int o = 1; o < SCAN_B; o <<= 1) {
        int t = (threadIdx.x >= o) ? sm[threadIdx.x - o] : 0;
        __syncthreads();
        sm[threadIdx.x] += t;
        __syncthreads();
    }
    if (i < n) g_incl[i] = sm[threadIdx.x];
    if (threadIdx.x == SCAN_B - 1) g_poff[blockIdx.x] = sm[SCAN_B - 1];
}

__global__ void k_scan2() {
    __shared__ int sm[512];
    int i = threadIdx.x;
    int v = (i < NBLK_SCAN) ? g_poff[i] : 0;
    sm[i] = v;
    __syncthreads();
#pragma unroll
    for (int o = 1; o < 512; o <<= 1) {
        int t = (i >= o) ? sm[i - o] : 0;
        __syncthreads();
        sm[i] += t;
        __syncthreads();
    }
    if (i < NBLK_SCAN) g_poff[i] = sm[i] - v;   // exclusive
}

__global__ void k_scan3(int n) {
    int i = blockIdx.x * blockDim.x + threadIdx.x;
    if (i >= n) return;
    int c = g_cnt[i];
    int rs = g_incl[i] - c + g_poff[i >> 8];
    g_rowstart[i] = rs;
    g_cur[i] = rs;
}

__global__ void k_place(const void* __restrict__ ei, int E) {
    int e = blockIdx.x * blockDim.x + threadIdx.x;
    if (e >= E) return;
    int s = load_idx(ei, e);
    int d = load_idx(ei, (long long)E + e);
    if ((unsigned)s >= NODES || (unsigned)d >= NODES) return;
    int pos = atomicAdd(&g_cur[d], 1);
    g_csr[pos] = s;
}

// ---------------------------------------------------------------------------
// fp16 GEMM, full-K single tile (same as R10 — measured at its floor):
//   g_half[row][c] = fp16( (sum_k A[row][k] * W[k][c]) * rsqrt(cnt[row]+1) )
// ---------------------------------------------------------------------------
#define SROW 136   // half stride (272 B): conflict-free ldmatrix

__global__ void __launch_bounds__(256)
k_gemm_f16(const float* __restrict__ x, int n, int use_h) {
    extern __shared__ __half smem[];
    __half* As = smem;
    __half* Ws = smem + 128 * SROW;

    int tid  = threadIdx.x;
    int wid  = tid >> 5;
    int lane = tid & 31;
    int gq   = lane >> 2;
    int tq   = lane & 3;
    int warp_m = wid & 1;
    int warp_n = wid >> 1;
    int row0 = blockIdx.x * 128;

    const __half* Wg = use_h ? g_w2h : g_w1h;

    float acc[4][4][4];
#pragma unroll
    for (int mt = 0; mt < 4; mt++)
#pragma unroll
        for (int j = 0; j < 4; j++)
#pragma unroll
            for (int r = 0; r < 4; r++) acc[mt][j][r] = 0.f;

    unsigned a_base[4], b_base[2];
    {
        int arow = lane & 15;
        int akof = ((lane >> 4) & 1) * 8;
#pragma unroll
        for (int mt = 0; mt < 4; mt++)
            a_base[mt] = (unsigned)__cvta_generic_to_shared(
                &As[(warp_m * 64 + mt * 16 + arow) * SROW + akof]);
        int krow = lane & 15;
        int nof  = ((lane >> 4) & 1) * 8;
#pragma unroll
        for (int nt2 = 0; nt2 < 2; nt2++)
            b_base[nt2] = (unsigned)__cvta_generic_to_shared(
                &Ws[krow * SROW + warp_n * 32 + nt2 * 16 + nof]);
    }

    if (!use_h) {
        // W via cp.async, A staged from fp32 x via LDG+cvt+STS
#pragma unroll
        for (int i = 0; i < 8; i++) {
            int slot = tid + i * 256;
            int r   = slot >> 4;
            int c16 = slot & 15;
            unsigned dw = (unsigned)__cvta_generic_to_shared(&Ws[r * SROW + c16 * 8]);
            asm volatile("cp.async.ca.shared.global [%0], [%1], 16;"
                         :: "r"(dw), "l"(Wg + r * 128 + c16 * 8));
        }
        asm volatile("cp.async.commit_group;");

        const float4* X4 = (const float4*)x;
#pragma unroll
        for (int i = 0; i < 8; i++) {
            int slot = tid + i * 256;
            int r   = slot >> 4;
            int c16 = slot & 15;
            int gr = row0 + r;
            float4 v0 = make_float4(0.f, 0.f, 0.f, 0.f);
            float4 v1 = v0;
            if (gr < n) {
                v0 = X4[(long long)gr * 32 + c16 * 2];
                v1 = X4[(long long)gr * 32 + c16 * 2 + 1];
            }
            uint4 d;
            *(__half2*)&d.x = __floats2half2_rn(v0.x, v0.y);
            *(__half2*)&d.y = __floats2half2_rn(v0.z, v0.w);
            *(__half2*)&d.z = __floats2half2_rn(v1.x, v1.y);
            *(__half2*)&d.w = __floats2half2_rn(v1.z, v1.w);
            *(uint4*)&As[r * SROW + c16 * 8] = d;
        }
        asm volatile("cp.async.wait_group 0;");
        __syncthreads();

#pragma unroll
        for (int ks = 0; ks < 8; ks++) {
            unsigned a[4][4], b[2][4];
#pragma unroll
            for (int mt = 0; mt < 4; mt++)
                asm volatile(
                    "ldmatrix.sync.aligned.m8n8.x4.shared.b16 {%0,%1,%2,%3}, [%4];"
                    : "=r"(a[mt][0]), "=r"(a[mt][1]), "=r"(a[mt][2]), "=r"(a[mt][3])
                    : "r"(a_base[mt] + ks * 32));
#pragma unroll
            for (int nt2 = 0; nt2 < 2; nt2++)
                asm volatile(
                    "ldmatrix.sync.aligned.m8n8.x4.trans.shared.b16 {%0,%1,%2,%3}, [%4];"
                    : "=r"(b[nt2][0]), "=r"(b[nt2][1]), "=r"(b[nt2][2]), "=r"(b[nt2][3])
                    : "r"(b_base[nt2] + ks * 16 * SROW * 2));
#pragma unroll
            for (int nt2 = 0; nt2 < 2; nt2++)
#pragma unroll
                for (int h8 = 0; h8 < 2; h8++) {
                    int j = nt2 * 2 + h8;
#pragma unroll
                    for (int mt = 0; mt < 4; mt++)
                        asm volatile(
                            "mma.sync.aligned.m16n8k16.row.col.f32.f16.f16.f32 "
                            "{%0,%1,%2,%3}, {%4,%5,%6,%7}, {%8,%9}, {%0,%1,%2,%3};"
                            : "+f"(acc[mt][j][0]), "+f"(acc[mt][j][1]),
                              "+f"(acc[mt][j][2]), "+f"(acc[mt][j][3])
                            : "r"(a[mt][0]), "r"(a[mt][1]),
                              "r"(a[mt][2]), "r"(a[mt][3]),
                              "r"(b[nt2][h8 * 2]), "r"(b[nt2][h8 * 2 + 1]));
                }
        }
    } else {
        // both via cp.async, two k-split commit groups
        const __half* Ag = g_h2;
#pragma unroll
        for (int grp = 0; grp < 2; grp++) {
#pragma unroll
            for (int i = 0; i < 4; i++) {
                int slot = tid + i * 256;       // 0..1023
                int r   = slot >> 3;            // 0..127
                int c16 = (slot & 7) + grp * 8;
                unsigned da = (unsigned)__cvta_generic_to_shared(&As[r * SROW + c16 * 8]);
                const __half* sa = Ag + (long long)(row0 + r) * 128 + c16 * 8;
                int va = (row0 + r < n) ? 16 : 0;
                asm volatile("cp.async.ca.shared.global [%0], [%1], 16, %2;"
                             :: "r"(da), "l"(sa), "r"(va));
                int wrow = grp * 64 + (slot >> 4);
                int wchk = slot & 15;
                unsigned dw = (unsigned)__cvta_generic_to_shared(&Ws[wrow * SROW + wchk * 8]);
                asm volatile("cp.async.ca.shared.global [%0], [%1], 16;"
                             :: "r"(dw), "l"(Wg + wrow * 128 + wchk * 8));
            }
            asm volatile("cp.async.commit_group;");
        }

        asm volatile("cp.async.wait_group 1;");
        __syncthreads();
#pragma unroll
        for (int ks = 0; ks < 4; ks++) {
            unsigned a[4][4], b[2][4];
#pragma unroll
            for (int mt = 0; mt < 4; mt++)
                asm volatile(
                    "ldmatrix.sync.aligned.m8n8.x4.shared.b16 {%0,%1,%2,%3}, [%4];"
                    : "=r"(a[mt][0]), "=r"(a[mt][1]), "=r"(a[mt][2]), "=r"(a[mt][3])
                    : "r"(a_base[mt] + ks * 32));
#pragma unroll
            for (int nt2 = 0; nt2 < 2; nt2++)
                asm volatile(
                    "ldmatrix.sync.aligned.m8n8.x4.trans.shared.b16 {%0,%1,%2,%3}, [%4];"
                    : "=r"(b[nt2][0]), "=r"(b[nt2][1]), "=r"(b[nt2][2]), "=r"(b[nt2][3])
                    : "r"(b_base[nt2] + ks * 16 * SROW * 2));
#pragma unroll
            for (int nt2 = 0; nt2 < 2; nt2++)
#pragma unroll
                for (int h8 = 0; h8 < 2; h8++) {
                    int j = nt2 * 2 + h8;
#pragma unroll
                    for (int mt = 0; mt < 4; mt++)
                        asm volatile(
                            "mma.sync.aligned.m16n8k16.row.col.f32.f16.f16.f32 "
                            "{%0,%1,%2,%3}, {%4,%5,%6,%7}, {%8,%9}, {%0,%1,%2,%3};"
                            : "+f"(acc[mt][j][0]), "+f"(acc[mt][j][1]),
                              "+f"(acc[mt][j][2]), "+f"(acc[mt][j][3])
                            : "r"(a[mt][0]), "r"(a[mt][1]),
                              "r"(a[mt][2]), "r"(a[mt][3]),
                              "r"(b[nt2][h8 * 2]), "r"(b[nt2][h8 * 2 + 1]));
                }
        }
        asm volatile("cp.async.wait_group 0;");
        __syncthreads();
#pragma unroll
        for (int ks = 4; ks < 8; ks++) {
            unsigned a[4][4], b[2][4];
#pragma unroll
            for (int mt = 0; mt < 4; mt++)
                asm volatile(
                    "ldmatrix.sync.aligned.m8n8.x4.shared.b16 {%0,%1,%2,%3}, [%4];"
                    : "=r"(a[mt][0]), "=r"(a[mt][1]), "=r"(a[mt][2]), "=r"(a[mt][3])
                    : "r"(a_base[mt] + ks * 32));
#pragma unroll
            for (int nt2 = 0; nt2 < 2; nt2++)
                asm volatile(
                    "ldmatrix.sync.aligned.m8n8.x4.trans.shared.b16 {%0,%1,%2,%3}, [%4];"
                    : "=r"(b[nt2][0]), "=r"(b[nt2][1]), "=r"(b[nt2][2]), "=r"(b[nt2][3])
                    : "r"(b_base[nt2] + ks * 16 * SROW * 2));
#pragma unroll
            for (int nt2 = 0; nt2 < 2; nt2++)
#pragma unroll
                for (int h8 = 0; h8 < 2; h8++) {
                    int j = nt2 * 2 + h8;
#pragma unroll
                    for (int mt = 0; mt < 4; mt++)
                        asm volatile(
                            "mma.sync.aligned.m16n8k16.row.col.f32.f16.f16.f32 "
                            "{%0,%1,%2,%3}, {%4,%5,%6,%7}, {%8,%9}, {%0,%1,%2,%3};"
                            : "+f"(acc[mt][j][0]), "+f"(acc[mt][j][1]),
                              "+f"(acc[mt][j][2]), "+f"(acc[mt][j][3])
                            : "r"(a[mt][0]), "r"(a[mt][1]),
                              "r"(a[mt][2]), "r"(a[mt][3]),
                              "r"(b[nt2][h8 * 2]), "r"(b[nt2][h8 * 2 + 1]));
                }
        }
    }

    // epilogue: dinv = rsqrt(cnt+1), convert to fp16, write g_half
#pragma unroll
    for (int mt = 0; mt < 4; mt++) {
        int rlo = row0 + warp_m * 64 + mt * 16 + gq;
        int rhi = rlo + 8;
        float dlo = (rlo < n) ? rsqrtf((float)g_cnt[rlo] + 1.0f) : 0.f;
        float dhi = (rhi < n) ? rsqrtf((float)g_cnt[rhi] + 1.0f) : 0.f;
#pragma unroll
        for (int j = 0; j < 4; j++) {
            int c = warp_n * 32 + j * 8 + 2 * tq;
            if (rlo < n)
                *(__half2*)&g_half[rlo * 128 + c] =
                    __floats2half2_rn(acc[mt][j][0] * dlo, acc[mt][j][1] * dlo);
            if (rhi < n)
                *(__half2*)&g_half[rhi * 128 + c] =
                    __floats2half2_rn(acc[mt][j][2] * dhi, acc[mt][j][3] * dhi);
        }
    }
}

// ---------------------------------------------------------------------------
// Aggregate (warp per node, fp16 gather, fp32 accumulate, unroll x8).
// ---------------------------------------------------------------------------
__device__ __forceinline__ void add_row(float4& acc, uint2 v) {
    float2 p0 = __half22float2(*(__half2*)&v.x);
    float2 p1 = __half22float2(*(__half2*)&v.y);
    acc.x += p0.x; acc.y += p0.y; acc.z += p1.x; acc.w += p1.y;
}

template <int FINAL>
__global__ void k_agg(const float* __restrict__ b,
                      const float* __restrict__ Wfc,
                      const float* __restrict__ bfc,
                      float* __restrict__ out,
                      int n) {
    int widx = (blockIdx.x * blockDim.x + threadIdx.x) >> 5;
    int q = threadIdx.x & 31;
    if (widx >= n) return;

    const uint2* gh = (const uint2*)g_half;
    int base = g_rowstart[widx];
    int cnt  = g_cnt[widx];
    int end  = base + cnt;

    float4 acc = make_float4(0.f, 0.f, 0.f, 0.f);
    add_row(acc, gh[widx * 32 + q]);          // self-loop term

    int e = base;
    for (; e + 8 <= end; e += 8) {
        uint2 v0 = gh[g_csr[e]     * 32 + q];
        uint2 v1 = gh[g_csr[e + 1] * 32 + q];
        uint2 v2 = gh[g_csr[e + 2] * 32 + q];
        uint2 v3 = gh[g_csr[e + 3] * 32 + q];
        uint2 v4 = gh[g_csr[e + 4] * 32 + q];
        uint2 v5 = gh[g_csr[e + 5] * 32 + q];
        uint2 v6 = gh[g_csr[e + 6] * 32 + q];
        uint2 v7 = gh[g_csr[e + 7] * 32 + q];
        add_row(acc, v0); add_row(acc, v1); add_row(acc, v2); add_row(acc, v3);
        add_row(acc, v4); add_row(acc, v5); add_row(acc, v6); add_row(acc, v7);
    }
    for (; e + 2 <= end; e += 2) {
        uint2 v0 = gh[g_csr[e]     * 32 + q];
        uint2 v1 = gh[g_csr[e + 1] * 32 + q];
        add_row(acc, v0); add_row(acc, v1);
    }
    if (e < end) add_row(acc, gh[g_csr[e] * 32 + q]);

    float dv = rsqrtf((float)cnt + 1.0f);
    float4 bb = ((const float4*)b)[q];
    float4 h;
    h.x = fmaxf(dv * acc.x + bb.x, 0.f);
    h.y = fmaxf(dv * acc.y + bb.y, 0.f);
    h.z = fmaxf(dv * acc.z + bb.z, 0.f);
    h.w = fmaxf(dv * acc.w + bb.w, 0.f);

    if (!FINAL) {
        uint2 st;
        *(__half2*)&st.x = __floats2half2_rn(h.x, h.y);
        *(__half2*)&st.y = __floats2half2_rn(h.z, h.w);
        ((uint2*)g_h2)[widx * 32 + q] = st;
    } else {
        const float4* w4 = (const float4*)Wfc;
        float4 w0 = w4[q * 2];
        float4 w1 = w4[q * 2 + 1];
        float l0 = h.x * w0.x + h.y * w0.z + h.z * w1.x + h.w * w1.z;
        float l1 = h.x * w0.y + h.y * w0.w + h.z * w1.y + h.w * w1.w;
#pragma unroll
        for (int o = 16; o > 0; o >>= 1) {
            l0 += __shfl_xor_sync(0xffffffffu, l0, o);
            l1 += __shfl_xor_sync(0xffffffffu, l1, o);
        }
        if (q == 0) {
            l0 += bfc[0];
            l1 += bfc[1];
            float m = fmaxf(l0, l1);
            float z = m + logf(expf(l0 - m) + expf(l1 - m));
            out[widx * 2]     = l0 - z;
            out[widx * 2 + 1] = l1 - z;
        }
    }
}

// ---------------------------------------------------------------------------
extern "C" void kernel_launch(void* const* d_in, const int* in_sizes, int n_in,
                              void* d_out, int out_size) {
    const float* x   = (const float*)d_in[0];
    const void*  ei  = d_in[1];
    const float* W1  = (const float*)d_in[2];
    const float* b1  = (const float*)d_in[3];
    const float* W2  = (const float*)d_in[4];
    const float* b2  = (const float*)d_in[5];
    const float* Wfc = (const float*)d_in[6];
    const float* bfc = (const float*)d_in[7];
    float*       out = (float*)d_out;

    int n = in_sizes[0] / FEAT;
    int E = in_sizes[1] / 2;

    int tb = 256;
    int node_blocks = (n + tb - 1) / tb;
    int edge_blocks = (E + tb - 1) / tb;
    int gemm_blocks = (n + 127) / 128;
    int warp_blocks = (int)(((long long)n * 32 + tb - 1) / tb);

    static int once = 0;
    static cudaStream_t s2;
    static cudaEvent_t ev_fork, ev_join;
    int gemm_smem = 2 * 128 * SROW * (int)sizeof(__half);   // 69632
    if (!once) {
        cudaFuncSetAttribute(k_gemm_f16,
                             cudaFuncAttributeMaxDynamicSharedMemorySize, gemm_smem);
        cudaStreamCreateWithFlags(&s2, cudaStreamNonBlocking);
        cudaEventCreateWithFlags(&ev_fork, cudaEventDisableTiming);
        cudaEventCreateWithFlags(&ev_join, cudaEventDisableTiming);
        once = 1;
    }

    // main stream: init + histogram (everything depends on these)
    k_init<<<node_blocks, tb>>>(ei, n);
    k_hist<<<edge_blocks, tb>>>(ei, E);

    // fork: CSR finalize on s2, concurrent with prep + layer-1 GEMM
    cudaEventRecord(ev_fork, 0);
    cudaStreamWaitEvent(s2, ev_fork, 0);
    k_scan1<<<NBLK_SCAN, SCAN_B, 0, s2>>>(n);
    k_scan2<<<1, 512, 0, s2>>>();
    k_scan3<<<node_blocks, tb, 0, s2>>>(n);
    k_place<<<edge_blocks, tb, 0, s2>>>(ei, E);
    cudaEventRecord(ev_join, s2);

    // main stream: weight conversion + layer-1 GEMM (needs only g_cnt)
    k_prep<<<32, tb>>>(W1, W2);
    k_gemm_f16<<<gemm_blocks, tb, gemm_smem>>>(x, n, 0);

    // join: aggregate needs both CSR and g_half
    cudaStreamWaitEvent(0, ev_join, 0);
    k_agg<0><<<warp_blocks, tb>>>(b1, nullptr, nullptr, nullptr, n);

    // layer 2 + fused FC/log_softmax
    k_gemm_f16<<<gemm_blocks, tb, gemm_smem>>>(x, n, 1);
    k_agg<1><<<warp_blocks, tb>>>(b2, Wfc, bfc, out, n);
}